// round 3
// baseline (speedup 1.0000x reference)
#include <cuda_runtime.h>
#include <cuda_bf16.h>
#include <stdint.h>
#include <stddef.h>

#define BDIM 4096
#define INDIM 2048
#define HDIM 2048
#define KDIM 4096   // IN + H
#define NDIM 8192   // 4 * H

// ---------------- scratch: permuted tf32 weights Bt[n'][k] ----------------
__device__ float g_Bt[(size_t)NDIM * KDIM];

// ---------------- PTX helpers ----------------
__device__ __forceinline__ uint32_t smem_u32(const void* p) {
    uint32_t a;
    asm("{ .reg .u64 t; cvta.to.shared.u64 t, %1; cvt.u32.u64 %0, t; }" : "=r"(a) : "l"(p));
    return a;
}
#define SWZ128(o) ((o) ^ (((o) >> 3) & 0x70))

#define LDSM4(r, addr) \
    asm volatile("ldmatrix.sync.aligned.m8n8.x4.shared.b16 {%0,%1,%2,%3}, [%4];" \
        : "=r"((r)[0]), "=r"((r)[1]), "=r"((r)[2]), "=r"((r)[3]) : "r"(addr))

// tf32 mma m16n8k8 (sm_80+, legal under compute_103)
#define MMATF32(d, a, b0, b1) \
    asm volatile("mma.sync.aligned.m16n8k8.row.col.f32.tf32.tf32.f32 " \
        "{%0,%1,%2,%3}, {%4,%5,%6,%7}, {%8,%9}, {%0,%1,%2,%3};" \
        : "+f"((d)[0]), "+f"((d)[1]), "+f"((d)[2]), "+f"((d)[3]) \
        : "r"((a)[0]), "r"((a)[1]), "r"((a)[2]), "r"((a)[3]), "r"(b0), "r"(b1))

__device__ __forceinline__ uint32_t cvt_tf32(uint32_t x) {
    uint32_t o;
    asm("cvt.rna.tf32.f32 %0, %1;" : "=r"(o) : "f"(__uint_as_float(x)));
    return o;
}
__device__ __forceinline__ float cvt_tf32f(float x) {
    uint32_t o;
    asm("cvt.rna.tf32.f32 %0, %1;" : "=r"(o) : "f"(x));
    return __uint_as_float(o);
}

#define CP_ASYNC16(s, g) \
    asm volatile("cp.async.cg.shared.global [%0], [%1], 16;" :: "r"(s), "l"(g))
#define CP_COMMIT() asm volatile("cp.async.commit_group;" ::: "memory")
#define CP_WAIT0()  asm volatile("cp.async.wait_group 0;" ::: "memory")
#define CP_WAIT1()  asm volatile("cp.async.wait_group 1;" ::: "memory")

// ---------------- Kernel 1: transpose + tf32-round weights into permuted Bt ----------------
// column permutation: for gate g, output unit j:  n' = (j>>3)*32 + g*8 + (j&7)
// so each 32-wide column group holds {i,f,o,g} x 8 consecutive j.
__global__ void prep_w_kernel(
    const float* __restrict__ w0, const float* __restrict__ w1,
    const float* __restrict__ w2, const float* __restrict__ w3,
    const float* __restrict__ w4, const float* __restrict__ w5,
    const float* __restrict__ w6, const float* __restrict__ w7) {
    __shared__ float t[64][33];
    int z = blockIdx.z;
    const float* w;
    switch (z) {
        case 0: w = w0; break; case 1: w = w1; break;
        case 2: w = w2; break; case 3: w = w3; break;
        case 4: w = w4; break; case 5: w = w5; break;
        case 6: w = w6; break; default: w = w7; break;
    }
    int k0 = blockIdx.x * 64;
    int j0 = blockIdx.y * 32;
    int tx = threadIdx.x, ty = threadIdx.y;
#pragma unroll
    for (int i = 0; i < 8; i++) {
        int r = ty + i * 8;
        t[r][tx] = w[(size_t)(k0 + r) * 2048 + j0 + tx];
    }
    __syncthreads();
    int gate = z & 3;
    int koff = (z >> 2) * 2048;
#pragma unroll
    for (int i = 0; i < 4; i++) {
        int jj = ty + i * 8;
        int j = j0 + jj;
        float v0 = cvt_tf32f(t[2 * tx][jj]);
        float v1 = cvt_tf32f(t[2 * tx + 1][jj]);
        size_t np = (size_t)((j >> 3) * 32 + gate * 8 + (j & 7));
        size_t off = np * KDIM + koff + k0 + 2 * tx;
        *reinterpret_cast<float2*>(g_Bt + off) = make_float2(v0, v1);
    }
}

// ---------------- Kernel 2: fused TF32 GEMM + LSTM epilogue ----------------
// CTA tile M=128, N=256, K-tile=64 (2 subtiles of k32 with 128B rows), double buffered.
#define TILE_M 128
#define TILE_N 256
#define TILE_K 64
#define SM_TILES 1024
#define ST_A 0                    // 2 subtiles x 16KB = 32KB
#define ST_B (32 * 1024)          // 2 subtiles x 32KB = 64KB
#define STAGE_BYTES (96 * 1024)
#define GEMM_SMEM (1024 + 2 * STAGE_BYTES)
#define K_ITERS (KDIM / TILE_K)   // 64

__device__ __forceinline__ void load_A_async(const float* __restrict__ x,
                                             const float* __restrict__ h,
                                             int m0, int it, uint32_t sdst, int tid) {
    const float* src = (it < 32) ? x : h;
    int kbase = (it * TILE_K) & 2047;
#pragma unroll
    for (int i = 0; i < 8; i++) {
        int q = tid + i * 256;
        int r = q >> 4, cu = q & 15, c = cu >> 3, u = cu & 7;
        const void* gp = src + (size_t)(m0 + r) * 2048 + kbase + c * 32 + u * 4;
        uint32_t off = (uint32_t)(r * 128 + u * 16);
        CP_ASYNC16(sdst + (uint32_t)c * 16384 + SWZ128(off), gp);
    }
}
__device__ __forceinline__ void load_B_async(int n0, int it, uint32_t sdst, int tid) {
    int kbase = it * TILE_K;
#pragma unroll
    for (int i = 0; i < 16; i++) {
        int q = tid + i * 256;
        int r = q >> 4, cu = q & 15, c = cu >> 3, u = cu & 7;
        const void* gp = g_Bt + (size_t)(n0 + r) * KDIM + kbase + c * 32 + u * 4;
        uint32_t off = (uint32_t)(r * 128 + u * 16);
        CP_ASYNC16(sdst + (uint32_t)c * 32768 + SWZ128(off), gp);
    }
}

__device__ __forceinline__ float sigm(float v) { return 1.0f / (1.0f + __expf(-v)); }
__device__ __forceinline__ float tanh_fast(float v) { return 2.0f / (1.0f + __expf(-2.0f * v)) - 1.0f; }

__global__ __launch_bounds__(256, 1) void gemm_lstm_kernel(
    const float* __restrict__ x, const float* __restrict__ h,
    const float* __restrict__ cin,
    const float* __restrict__ bi, const float* __restrict__ bf,
    const float* __restrict__ bo, const float* __restrict__ bc,
    float* __restrict__ out) {
    extern __shared__ char smem[];
    uint32_t sbase = smem_u32(smem);
    int tid = threadIdx.x;
    int wid = tid >> 5, lane = tid & 31;
    int mt = blockIdx.x & 31;       // M fast-varying: wave shares B tiles in L2
    int nt = blockIdx.x >> 5;
    int m0 = mt * TILE_M, n0 = nt * TILE_N;
    int warp_m = wid & 3, warp_n = wid >> 2;

    // A fragment addressing (per m16 frag; 128B rows, SW128)
    uint32_t aoff[2], axor[2];
#pragma unroll
    for (int fm = 0; fm < 2; fm++) {
        int arow = warp_m * 32 + fm * 16 + (lane & 15);
        aoff[fm] = (uint32_t)(arow * 128);
        axor[fm] = (uint32_t)((arow & 7) << 4);
    }
    uint32_t asub = (uint32_t)((lane >> 4) << 4);

    // B fragment addressing: x4 per p covers n-frags 2p,2p+1 over k8
    uint32_t boff[8], bxor;
#pragma unroll
    for (int p = 0; p < 8; p++) {
        int brow = warp_n * 128 + p * 16 + (lane & 7) + ((lane >> 4) & 1) * 8;
        boff[p] = (uint32_t)(brow * 128);
    }
    bxor = (uint32_t)((lane & 7) << 4);
    uint32_t bsub = (uint32_t)(((lane >> 3) & 1) << 4);

    float acc[2][16][4];
#pragma unroll
    for (int fm = 0; fm < 2; fm++)
#pragma unroll
        for (int fn = 0; fn < 16; fn++)
#pragma unroll
            for (int j = 0; j < 4; j++) acc[fm][fn][j] = 0.0f;

    // prologue: stage 0
    {
        uint32_t nb = sbase + SM_TILES;
        load_A_async(x, h, m0, 0, nb + ST_A, tid);
        load_B_async(n0, 0, nb + ST_B, tid);
        CP_COMMIT();
    }

#pragma unroll 1
    for (int it = 0; it < K_ITERS; ++it) {
        int s = it & 1;
        if (it + 1 < K_ITERS) {
            uint32_t nb = sbase + SM_TILES + (uint32_t)((it + 1) & 1) * STAGE_BYTES;
            load_A_async(x, h, m0, it + 1, nb + ST_A, tid);
            load_B_async(n0, it + 1, nb + ST_B, tid);
            CP_COMMIT();
            CP_WAIT1();
        } else {
            CP_WAIT0();
        }
        __syncthreads();

        uint32_t sb = sbase + SM_TILES + (uint32_t)s * STAGE_BYTES;
#pragma unroll
        for (int ks = 0; ks < 8; ks++) {
            uint32_t cA = (uint32_t)(ks >> 2) * 16384;
            uint32_t cB = (uint32_t)(ks >> 2) * 32768;
            uint32_t colb = (uint32_t)((ks & 3) * 32);
            uint32_t ah[2][4], bb[8][4];
#pragma unroll
            for (int fm = 0; fm < 2; fm++) {
                LDSM4(ah[fm], sb + ST_A + cA + aoff[fm] + ((colb + asub) ^ axor[fm]));
#pragma unroll
                for (int j = 0; j < 4; j++) ah[fm][j] = cvt_tf32(ah[fm][j]);
            }
#pragma unroll
            for (int p = 0; p < 8; p++)
                LDSM4(bb[p], sb + ST_B + cB + boff[p] + ((colb + bsub) ^ bxor));
#pragma unroll
            for (int p = 0; p < 8; p++)
#pragma unroll
                for (int fm = 0; fm < 2; fm++) {
                    MMATF32(acc[fm][2 * p], ah[fm], bb[p][0], bb[p][1]);
                    MMATF32(acc[fm][2 * p + 1], ah[fm], bb[p][2], bb[p][3]);
                }
        }
        __syncthreads();
    }

    // -------- fused LSTM epilogue (columns are gate-interleaved: fn%4 = gate) --------
    // thread acc element (fm, fn, v): row = m0 + warp_m*32 + (lane>>2) + fm*16 + (v>=2)*8
    //   j = n0/4 + warp_n*32 + (fn>>2)*8 + (lane&3)*2 + (v&1)
    {
        int r_base = m0 + warp_m * 32 + (lane >> 2);
        int jb = (n0 >> 2) + warp_n * 32;
        float* outh = out;
        float* outc = out + (size_t)BDIM * HDIM;
#pragma unroll
        for (int fm = 0; fm < 2; fm++) {
#pragma unroll
            for (int q = 0; q < 4; q++) {
                int j0e = jb + q * 8 + (lane & 3) * 2;
                float2 vbi = *reinterpret_cast<const float2*>(bi + j0e);
                float2 vbf = *reinterpret_cast<const float2*>(bf + j0e);
                float2 vbo = *reinterpret_cast<const float2*>(bo + j0e);
                float2 vbc = *reinterpret_cast<const float2*>(bc + j0e);
                const float* gi = acc[fm][4 * q + 0];
                const float* gf = acc[fm][4 * q + 1];
                const float* go = acc[fm][4 * q + 2];
                const float* gg = acc[fm][4 * q + 3];
#pragma unroll
                for (int v2 = 0; v2 < 2; v2++) {
                    int row = r_base + fm * 16 + v2 * 8;
                    float2 cv = *reinterpret_cast<const float2*>(cin + (size_t)row * HDIM + j0e);
                    float2 hres, cres;
#pragma unroll
                    for (int e = 0; e < 2; e++) {
                        int idx = v2 * 2 + e;
                        float I = sigm(gi[idx] + (e ? vbi.y : vbi.x));
                        float F = sigm(gf[idx] + (e ? vbf.y : vbf.x));
                        float O = sigm(go[idx] + (e ? vbo.y : vbo.x));
                        float G = tanh_fast(gg[idx] + (e ? vbc.y : vbc.x));
                        float cc = (e ? cv.y : cv.x);
                        float ct = cc * F + I * G;
                        float ht = O * tanh_fast(ct);
                        if (e) { hres.y = ht; cres.y = ct; }
                        else   { hres.x = ht; cres.x = ct; }
                    }
                    *reinterpret_cast<float2*>(outh + (size_t)row * HDIM + j0e) = hres;
                    *reinterpret_cast<float2*>(outc + (size_t)row * HDIM + j0e) = cres;
                }
            }
        }
    }
}

// ---------------- host launch ----------------
extern "C" void kernel_launch(void* const* d_in, const int* in_sizes, int n_in,
                              void* d_out, int out_size) {
    const float* x = (const float*)d_in[0];
    const float* h = (const float*)d_in[1];
    const float* c = (const float*)d_in[2];
    const float* w_xi = (const float*)d_in[3];
    const float* w_xf = (const float*)d_in[4];
    const float* w_xo = (const float*)d_in[5];
    const float* w_xc = (const float*)d_in[6];
    const float* w_hi = (const float*)d_in[7];
    const float* w_hf = (const float*)d_in[8];
    const float* w_ho = (const float*)d_in[9];
    const float* w_hc = (const float*)d_in[10];
    const float* b_i = (const float*)d_in[11];
    const float* b_f = (const float*)d_in[12];
    const float* b_o = (const float*)d_in[13];
    const float* b_c = (const float*)d_in[14];
    float* out = (float*)d_out;

    cudaFuncSetAttribute(gemm_lstm_kernel, cudaFuncAttributeMaxDynamicSharedMemorySize, GEMM_SMEM);

    {
        dim3 grid(2048 / 64, 2048 / 32, 8);
        dim3 blk(32, 8);
        prep_w_kernel<<<grid, blk>>>(w_xi, w_xf, w_xo, w_xc, w_hi, w_hf, w_ho, w_hc);
    }
    gemm_lstm_kernel<<<1024, 256, GEMM_SMEM>>>(x, h, c, b_i, b_f, b_o, b_c, out);
    (void)in_sizes; (void)n_in; (void)out_size;
}

// round 4
// speedup vs baseline: 1.7854x; 1.7854x over previous
#include <cuda_runtime.h>
#include <cuda_fp16.h>
#include <stdint.h>
#include <stddef.h>

#define BDIM 4096
#define INDIM 2048
#define HDIM 2048
#define KDIM 4096   // IN + H
#define NDIM 8192   // 4 * H

// ---------------- scratch ----------------
__device__ __half g_A [(size_t)BDIM * KDIM];   // [x | h] as fp16
__device__ __half g_Bt[(size_t)NDIM * KDIM];   // permuted transposed weights as fp16

// ---------------- PTX helpers ----------------
__device__ __forceinline__ uint32_t smem_u32(const void* p) {
    uint32_t a;
    asm("{ .reg .u64 t; cvta.to.shared.u64 t, %1; cvt.u32.u64 %0, t; }" : "=r"(a) : "l"(p));
    return a;
}
#define SWZ128(o) ((o) ^ (((o) >> 3) & 0x70))

#define LDSM4(r, addr) \
    asm volatile("ldmatrix.sync.aligned.m8n8.x4.shared.b16 {%0,%1,%2,%3}, [%4];" \
        : "=r"((r)[0]), "=r"((r)[1]), "=r"((r)[2]), "=r"((r)[3]) : "r"(addr))

#define MMAF16(d, a, b0, b1) \
    asm volatile("mma.sync.aligned.m16n8k16.row.col.f32.f16.f16.f32 " \
        "{%0,%1,%2,%3}, {%4,%5,%6,%7}, {%8,%9}, {%0,%1,%2,%3};" \
        : "+f"((d)[0]), "+f"((d)[1]), "+f"((d)[2]), "+f"((d)[3]) \
        : "r"((a)[0]), "r"((a)[1]), "r"((a)[2]), "r"((a)[3]), "r"(b0), "r"(b1))

#define CP_ASYNC16(s, g) \
    asm volatile("cp.async.cg.shared.global [%0], [%1], 16;" :: "r"(s), "l"(g))
#define CP_COMMIT() asm volatile("cp.async.commit_group;" ::: "memory")
#define CP_WAITG(n) asm volatile("cp.async.wait_group %0;" :: "n"(n) : "memory")

// ---------------- Kernel 1: A = [x | h] -> fp16 ----------------
__global__ void prep_a_kernel(const float* __restrict__ x, const float* __restrict__ h) {
    size_t gid = (size_t)blockIdx.x * blockDim.x + threadIdx.x;
    size_t e = gid * 4;
    if (e >= (size_t)BDIM * KDIM) return;
    int b = (int)(e >> 12);
    int k = (int)(e & 4095);
    const float* src = (k < INDIM) ? (x + (size_t)b * INDIM + k)
                                   : (h + (size_t)b * HDIM + (k - INDIM));
    float4 v = *reinterpret_cast<const float4*>(src);
    __half2* p = reinterpret_cast<__half2*>(g_A + e);
    p[0] = __halves2half2(__float2half_rn(v.x), __float2half_rn(v.y));
    p[1] = __halves2half2(__float2half_rn(v.z), __float2half_rn(v.w));
}

// ---------------- Kernel 2: weights -> transposed, gate-permuted fp16 ----------------
// for gate g, output unit j:  n' = (j>>3)*32 + g*8 + (j&7)
__global__ void prep_w_kernel(
    const float* __restrict__ w0, const float* __restrict__ w1,
    const float* __restrict__ w2, const float* __restrict__ w3,
    const float* __restrict__ w4, const float* __restrict__ w5,
    const float* __restrict__ w6, const float* __restrict__ w7) {
    __shared__ float t[64][33];
    int z = blockIdx.z;
    const float* w;
    switch (z) {
        case 0: w = w0; break; case 1: w = w1; break;
        case 2: w = w2; break; case 3: w = w3; break;
        case 4: w = w4; break; case 5: w = w5; break;
        case 6: w = w6; break; default: w = w7; break;
    }
    int k0 = blockIdx.x * 64;
    int j0 = blockIdx.y * 32;
    int tx = threadIdx.x, ty = threadIdx.y;
#pragma unroll
    for (int i = 0; i < 8; i++) {
        int r = ty + i * 8;
        t[r][tx] = w[(size_t)(k0 + r) * 2048 + j0 + tx];
    }
    __syncthreads();
    int gate = z & 3;
    int koff = (z >> 2) * 2048;
#pragma unroll
    for (int i = 0; i < 4; i++) {
        int jj = ty + i * 8;
        int j = j0 + jj;
        __half v0 = __float2half_rn(t[2 * tx][jj]);
        __half v1 = __float2half_rn(t[2 * tx + 1][jj]);
        size_t np = (size_t)((j >> 3) * 32 + gate * 8 + (j & 7));
        size_t off = np * KDIM + koff + k0 + 2 * tx;
        *reinterpret_cast<__half2*>(g_Bt + off) = __halves2half2(v0, v1);
    }
}

// ---------------- Kernel 3: single-pass fp16 GEMM + fused LSTM ----------------
#define TILE_M 128
#define TILE_N 256
#define TILE_K 64
#define ST_A 0                     // 128 x 64 fp16 = 16KB
#define ST_B (16 * 1024)           // 256 x 64 fp16 = 32KB
#define STAGE_BYTES (48 * 1024)
#define NSTAGE 3
#define GEMM_SMEM (NSTAGE * STAGE_BYTES)
#define K_ITERS (KDIM / TILE_K)    // 64

__device__ __forceinline__ void load_A_async(int m0, int it, uint32_t sdst, int tid) {
    int k0 = it * TILE_K;
#pragma unroll
    for (int i = 0; i < 4; i++) {
        int q = tid + i * 256;
        int r = q >> 3, c = q & 7;
        const void* gp = g_A + (size_t)(m0 + r) * KDIM + k0 + c * 8;
        uint32_t off = (uint32_t)(r * 128 + c * 16);
        CP_ASYNC16(sdst + SWZ128(off), gp);
    }
}
__device__ __forceinline__ void load_B_async(int n0, int it, uint32_t sdst, int tid) {
    int k0 = it * TILE_K;
#pragma unroll
    for (int i = 0; i < 8; i++) {
        int q = tid + i * 256;
        int r = q >> 3, c = q & 7;
        const void* gp = g_Bt + (size_t)(n0 + r) * KDIM + k0 + c * 8;
        uint32_t off = (uint32_t)(r * 128 + c * 16);
        CP_ASYNC16(sdst + SWZ128(off), gp);
    }
}

__device__ __forceinline__ float sigm(float v) { return 1.0f / (1.0f + __expf(-v)); }
__device__ __forceinline__ float tanh_fast(float v) { return 2.0f / (1.0f + __expf(-2.0f * v)) - 1.0f; }

__global__ __launch_bounds__(256, 1) void gemm_lstm_kernel(
    const float* __restrict__ cin,
    const float* __restrict__ bi, const float* __restrict__ bf,
    const float* __restrict__ bo, const float* __restrict__ bc,
    float* __restrict__ out) {
    extern __shared__ char smem[];
    uint32_t sbase = smem_u32(smem);
    int tid = threadIdx.x;
    int wid = tid >> 5, lane = tid & 31;
    int mt = blockIdx.x & 31;       // M fast-varying: wave shares B tiles in L2
    int nt = blockIdx.x >> 5;
    int m0 = mt * TILE_M, n0 = nt * TILE_N;
    int warp_m = wid & 3, warp_n = wid >> 2;

    // A fragment addressing (128B rows, SW128); per m16 frag
    uint32_t aoff[2], axor[2];
#pragma unroll
    for (int fm = 0; fm < 2; fm++) {
        int arow = warp_m * 32 + fm * 16 + (lane & 15);
        aoff[fm] = (uint32_t)(arow * 128);
        axor[fm] = (uint32_t)((arow & 7) << 4);
    }
    uint32_t asub = (uint32_t)((lane >> 4) << 4);

    // B fragment addressing: x4 per p covers n-frags 2p,2p+1 over k16
    int brow = warp_n * 128 + (lane & 7) + ((lane >> 4) & 1) * 8;
    uint32_t boff0 = (uint32_t)(brow * 128);
    uint32_t bxor = (uint32_t)((brow & 7) << 4);
    uint32_t bsub = (uint32_t)(((lane >> 3) & 1) << 4);

    float acc[2][16][4];
#pragma unroll
    for (int fm = 0; fm < 2; fm++)
#pragma unroll
        for (int fn = 0; fn < 16; fn++)
#pragma unroll
            for (int j = 0; j < 4; j++) acc[fm][fn][j] = 0.0f;

    // prologue: stages 0,1
#pragma unroll
    for (int pi = 0; pi < 2; pi++) {
        uint32_t nb = sbase + (uint32_t)pi * STAGE_BYTES;
        load_A_async(m0, pi, nb + ST_A, tid);
        load_B_async(n0, pi, nb + ST_B, tid);
        CP_COMMIT();
    }

#pragma unroll 1
    for (int it = 0; it < K_ITERS; ++it) {
        if (it + 2 < K_ITERS) {
            int sidx = (it + 2) % NSTAGE;
            uint32_t nb = sbase + (uint32_t)sidx * STAGE_BYTES;
            load_A_async(m0, it + 2, nb + ST_A, tid);
            load_B_async(n0, it + 2, nb + ST_B, tid);
            CP_COMMIT();
            CP_WAITG(2);
        } else if (it + 1 < K_ITERS) {
            CP_WAITG(1);
        } else {
            CP_WAITG(0);
        }
        __syncthreads();

        uint32_t sb = sbase + (uint32_t)(it % NSTAGE) * STAGE_BYTES;
#pragma unroll
        for (int ks = 0; ks < 4; ks++) {
            uint32_t acb = (uint32_t)(ks * 32) + asub;
            uint32_t bcb = (uint32_t)(ks * 32) + bsub;
            uint32_t ah[2][4], bb[8][4];
#pragma unroll
            for (int fm = 0; fm < 2; fm++)
                LDSM4(ah[fm], sb + ST_A + aoff[fm] + (acb ^ axor[fm]));
#pragma unroll
            for (int p = 0; p < 8; p++)
                LDSM4(bb[p], sb + ST_B + boff0 + (uint32_t)(p * 2048) + (bcb ^ bxor));
#pragma unroll
            for (int p = 0; p < 8; p++)
#pragma unroll
                for (int fm = 0; fm < 2; fm++) {
                    MMAF16(acc[fm][2 * p], ah[fm], bb[p][0], bb[p][1]);
                    MMAF16(acc[fm][2 * p + 1], ah[fm], bb[p][2], bb[p][3]);
                }
        }
        __syncthreads();
    }

    // -------- fused LSTM epilogue (gate-interleaved columns: fn&3 = gate) --------
    {
        int r_base = m0 + warp_m * 32 + (lane >> 2);
        int jb = (n0 >> 2) + warp_n * 32;
        float* outh = out;
        float* outc = out + (size_t)BDIM * HDIM;
#pragma unroll
        for (int fm = 0; fm < 2; fm++) {
#pragma unroll
            for (int q = 0; q < 4; q++) {
                int j0e = jb + q * 8 + (lane & 3) * 2;
                float2 vbi = *reinterpret_cast<const float2*>(bi + j0e);
                float2 vbf = *reinterpret_cast<const float2*>(bf + j0e);
                float2 vbo = *reinterpret_cast<const float2*>(bo + j0e);
                float2 vbc = *reinterpret_cast<const float2*>(bc + j0e);
                const float* gi = acc[fm][4 * q + 0];
                const float* gf = acc[fm][4 * q + 1];
                const float* go = acc[fm][4 * q + 2];
                const float* gg = acc[fm][4 * q + 3];
#pragma unroll
                for (int v2 = 0; v2 < 2; v2++) {
                    int row = r_base + fm * 16 + v2 * 8;
                    float2 cv = *reinterpret_cast<const float2*>(cin + (size_t)row * HDIM + j0e);
                    float2 hres, cres;
#pragma unroll
                    for (int e = 0; e < 2; e++) {
                        int idx = v2 * 2 + e;
                        float I = sigm(gi[idx] + (e ? vbi.y : vbi.x));
                        float F = sigm(gf[idx] + (e ? vbf.y : vbf.x));
                        float O = sigm(go[idx] + (e ? vbo.y : vbo.x));
                        float G = tanh_fast(gg[idx] + (e ? vbc.y : vbc.x));
                        float cc = (e ? cv.y : cv.x);
                        float ct = cc * F + I * G;
                        float ht = O * tanh_fast(ct);
                        if (e) { hres.y = ht; cres.y = ct; }
                        else   { hres.x = ht; cres.x = ct; }
                    }
                    *reinterpret_cast<float2*>(outh + (size_t)row * HDIM + j0e) = hres;
                    *reinterpret_cast<float2*>(outc + (size_t)row * HDIM + j0e) = cres;
                }
            }
        }
    }
}

// ---------------- host launch ----------------
extern "C" void kernel_launch(void* const* d_in, const int* in_sizes, int n_in,
                              void* d_out, int out_size) {
    const float* x = (const float*)d_in[0];
    const float* h = (const float*)d_in[1];
    const float* c = (const float*)d_in[2];
    const float* w_xi = (const float*)d_in[3];
    const float* w_xf = (const float*)d_in[4];
    const float* w_xo = (const float*)d_in[5];
    const float* w_xc = (const float*)d_in[6];
    const float* w_hi = (const float*)d_in[7];
    const float* w_hf = (const float*)d_in[8];
    const float* w_ho = (const float*)d_in[9];
    const float* w_hc = (const float*)d_in[10];
    const float* b_i = (const float*)d_in[11];
    const float* b_f = (const float*)d_in[12];
    const float* b_o = (const float*)d_in[13];
    const float* b_c = (const float*)d_in[14];
    float* out = (float*)d_out;

    cudaFuncSetAttribute(gemm_lstm_kernel, cudaFuncAttributeMaxDynamicSharedMemorySize, GEMM_SMEM);

    {
        size_t total = (size_t)BDIM * KDIM / 4;
        int blocks = (int)((total + 255) / 256);
        prep_a_kernel<<<blocks, 256>>>(x, h);
    }
    {
        dim3 grid(2048 / 64, 2048 / 32, 8);
        dim3 blk(32, 8);
        prep_w_kernel<<<grid, blk>>>(w_xi, w_xf, w_xo, w_xc, w_hi, w_hf, w_ho, w_hc);
    }
    gemm_lstm_kernel<<<1024, 256, GEMM_SMEM>>>(c, b_i, b_f, b_o, b_c, out);
    (void)in_sizes; (void)n_in; (void)out_size;
}

// round 6
// speedup vs baseline: 2.8619x; 1.6029x over previous
#include <cuda_runtime.h>
#include <cuda_fp16.h>
#include <stdint.h>
#include <stddef.h>

#define BDIM 4096
#define INDIM 2048
#define HDIM 2048
#define KDIM 4096   // IN + H
#define NDIM 8192   // 4 * H

// ---------------- scratch ----------------
__device__ __half g_A [(size_t)BDIM * KDIM];   // [x | h] as fp16
__device__ __half g_Bt[(size_t)NDIM * KDIM];   // permuted transposed weights as fp16

// ---------------- PTX helpers ----------------
__device__ __forceinline__ uint32_t smem_u32(const void* p) {
    uint32_t a;
    asm("{ .reg .u64 t; cvta.to.shared.u64 t, %1; cvt.u32.u64 %0, t; }" : "=r"(a) : "l"(p));
    return a;
}
#define SWZ128(o) ((o) ^ (((o) >> 3) & 0x70))

#define LDSM4(r, addr) \
    asm volatile("ldmatrix.sync.aligned.m8n8.x4.shared.b16 {%0,%1,%2,%3}, [%4];" \
        : "=r"((r)[0]), "=r"((r)[1]), "=r"((r)[2]), "=r"((r)[3]) : "r"(addr))

#define MMAF16(d, a, b0, b1) \
    asm volatile("mma.sync.aligned.m16n8k16.row.col.f32.f16.f16.f32 " \
        "{%0,%1,%2,%3}, {%4,%5,%6,%7}, {%8,%9}, {%0,%1,%2,%3};" \
        : "+f"((d)[0]), "+f"((d)[1]), "+f"((d)[2]), "+f"((d)[3]) \
        : "r"((a)[0]), "r"((a)[1]), "r"((a)[2]), "r"((a)[3]), "r"(b0), "r"(b1))

#define CP_ASYNC16(s, g) \
    asm volatile("cp.async.cg.shared.global [%0], [%1], 16;" :: "r"(s), "l"(g))
#define CP_COMMIT() asm volatile("cp.async.commit_group;" ::: "memory")
#define CP_WAITG(n) asm volatile("cp.async.wait_group %0;" :: "n"(n) : "memory")

// ---------------- Kernel 1: A = [x | h] -> fp16 ----------------
__global__ void prep_a_kernel(const float* __restrict__ x, const float* __restrict__ h) {
    size_t gid = (size_t)blockIdx.x * blockDim.x + threadIdx.x;
    size_t e = gid * 4;
    if (e >= (size_t)BDIM * KDIM) return;
    int b = (int)(e >> 12);
    int k = (int)(e & 4095);
    const float* src = (k < INDIM) ? (x + (size_t)b * INDIM + k)
                                   : (h + (size_t)b * HDIM + (k - INDIM));
    float4 v = *reinterpret_cast<const float4*>(src);
    __half2* p = reinterpret_cast<__half2*>(g_A + e);
    p[0] = __halves2half2(__float2half_rn(v.x), __float2half_rn(v.y));
    p[1] = __halves2half2(__float2half_rn(v.z), __float2half_rn(v.w));
}

// ---------------- Kernel 2: weights -> transposed, gate-permuted fp16 ----------------
// for gate g, output unit j:  n' = (j>>3)*32 + g*8 + (j&7)
__global__ void prep_w_kernel(
    const float* __restrict__ w0, const float* __restrict__ w1,
    const float* __restrict__ w2, const float* __restrict__ w3,
    const float* __restrict__ w4, const float* __restrict__ w5,
    const float* __restrict__ w6, const float* __restrict__ w7) {
    __shared__ float t[64][33];
    int z = blockIdx.z;
    const float* w;
    switch (z) {
        case 0: w = w0; break; case 1: w = w1; break;
        case 2: w = w2; break; case 3: w = w3; break;
        case 4: w = w4; break; case 5: w = w5; break;
        case 6: w = w6; break; default: w = w7; break;
    }
    int k0 = blockIdx.x * 64;
    int j0 = blockIdx.y * 32;
    int tx = threadIdx.x, ty = threadIdx.y;
#pragma unroll
    for (int i = 0; i < 8; i++) {
        int r = ty + i * 8;
        t[r][tx] = w[(size_t)(k0 + r) * 2048 + j0 + tx];
    }
    __syncthreads();
    int gate = z & 3;
    int koff = (z >> 2) * 2048;
#pragma unroll
    for (int i = 0; i < 4; i++) {
        int jj = ty + i * 8;
        int j = j0 + jj;
        __half v0 = __float2half_rn(t[2 * tx][jj]);
        __half v1 = __float2half_rn(t[2 * tx + 1][jj]);
        size_t np = (size_t)((j >> 3) * 32 + gate * 8 + (j & 7));
        size_t off = np * KDIM + koff + k0 + 2 * tx;
        *reinterpret_cast<__half2*>(g_Bt + off) = __halves2half2(v0, v1);
    }
}

// ---------------- Kernel 3: fp16 GEMM (K-tile 128) + fused LSTM ----------------
#define TILE_M 128
#define TILE_N 256
#define TILE_K 128
#define ST_A 0                     // 2 subtiles x 16KB = 32KB
#define ST_B (32 * 1024)           // 2 subtiles x 32KB = 64KB
#define STAGE_BYTES (96 * 1024)
#define NSTAGE 2
#define GEMM_SMEM (NSTAGE * STAGE_BYTES)
#define K_ITERS (KDIM / TILE_K)    // 32

__device__ __forceinline__ void load_A_async(int m0, int it, uint32_t sdst, int tid) {
    int k0 = it * TILE_K;
#pragma unroll
    for (int i = 0; i < 8; i++) {
        int q = tid + i * 256;
        int r = q >> 4, cu = q & 15, c = cu >> 3, u = cu & 7;
        const void* gp = g_A + (size_t)(m0 + r) * KDIM + k0 + c * 64 + u * 8;
        uint32_t off = (uint32_t)(r * 128 + u * 16);
        CP_ASYNC16(sdst + (uint32_t)c * 16384 + SWZ128(off), gp);
    }
}
__device__ __forceinline__ void load_B_async(int n0, int it, uint32_t sdst, int tid) {
    int k0 = it * TILE_K;
#pragma unroll
    for (int i = 0; i < 16; i++) {
        int q = tid + i * 256;
        int r = q >> 4, cu = q & 15, c = cu >> 3, u = cu & 7;
        const void* gp = g_Bt + (size_t)(n0 + r) * KDIM + k0 + c * 64 + u * 8;
        uint32_t off = (uint32_t)(r * 128 + u * 16);
        CP_ASYNC16(sdst + (uint32_t)c * 32768 + SWZ128(off), gp);
    }
}

__device__ __forceinline__ float sigm(float v) { return 1.0f / (1.0f + __expf(-v)); }
__device__ __forceinline__ float tanh_fast(float v) { return 2.0f / (1.0f + __expf(-2.0f * v)) - 1.0f; }

__global__ __launch_bounds__(256, 1) void gemm_lstm_kernel(
    const float* __restrict__ cin,
    const float* __restrict__ bi, const float* __restrict__ bf,
    const float* __restrict__ bo, const float* __restrict__ bc,
    float* __restrict__ out) {
    extern __shared__ char smem[];
    uint32_t sbase = smem_u32(smem);
    int tid = threadIdx.x;
    int wid = tid >> 5, lane = tid & 31;
    int mt = blockIdx.x & 31;       // M fast-varying: wave shares B tiles in L2
    int nt = blockIdx.x >> 5;
    int m0 = mt * TILE_M, n0 = nt * TILE_N;
    int warp_m = wid & 1, warp_n = wid >> 1;   // 2(M) x 4(N); warp tile 64x64

    uint32_t xorv = (uint32_t)((lane & 7) << 4);

    // A fragment addressing: 4 m16 frags
    uint32_t aoff[4];
#pragma unroll
    for (int fm = 0; fm < 4; fm++) {
        int arow = warp_m * 64 + fm * 16 + (lane & 15);
        aoff[fm] = (uint32_t)(arow * 128);
    }
    uint32_t asub = (uint32_t)((lane >> 4) << 4);

    // B fragment addressing: 4 x4-loads, each covers n-frags 2p,2p+1 over k16
    uint32_t boff[4];
#pragma unroll
    for (int p = 0; p < 4; p++) {
        int brow = warp_n * 64 + p * 16 + (lane & 7) + ((lane >> 4) & 1) * 8;
        boff[p] = (uint32_t)(brow * 128);
    }
    uint32_t bsub = (uint32_t)(((lane >> 3) & 1) << 4);

    float acc[4][8][4];
#pragma unroll
    for (int fm = 0; fm < 4; fm++)
#pragma unroll
        for (int fn = 0; fn < 8; fn++)
#pragma unroll
            for (int j = 0; j < 4; j++) acc[fm][fn][j] = 0.0f;

    // prologue: stage 0 only (distance-1 prefetch, 2 stages)
    {
        uint32_t nb = sbase;
        load_A_async(m0, 0, nb + ST_A, tid);
        load_B_async(n0, 0, nb + ST_B, tid);
        CP_COMMIT();
    }

    uint32_t ah[2][4][4], bb[2][4][4];

#pragma unroll 1
    for (int it = 0; it < K_ITERS; ++it) {
        if (it + 1 < K_ITERS) {
            uint32_t nb = sbase + (uint32_t)((it + 1) & 1) * STAGE_BYTES;
            load_A_async(m0, it + 1, nb + ST_A, tid);
            load_B_async(n0, it + 1, nb + ST_B, tid);
            CP_COMMIT();
            CP_WAITG(1);
        } else {
            CP_WAITG(0);
        }
        __syncthreads();

        uint32_t sb = sbase + (uint32_t)(it & 1) * STAGE_BYTES;
        uint32_t sA = sb + ST_A, sB = sb + ST_B;

        // preload ks=0 fragments
        {
#pragma unroll
            for (int fm = 0; fm < 4; fm++)
                LDSM4(ah[0][fm], sA + aoff[fm] + (asub ^ xorv));
#pragma unroll
            for (int p = 0; p < 4; p++)
                LDSM4(bb[0][p], sB + boff[p] + (bsub ^ xorv));
        }

#pragma unroll
        for (int ks = 0; ks < 8; ks++) {
            int cur = ks & 1, nxt = cur ^ 1;
            if (ks < 7) {
                int kn = ks + 1;
                uint32_t cA = (uint32_t)(kn >> 2) * 16384;
                uint32_t cB = (uint32_t)(kn >> 2) * 32768;
                uint32_t colb = (uint32_t)((kn & 3) * 32);
#pragma unroll
                for (int fm = 0; fm < 4; fm++)
                    LDSM4(ah[nxt][fm], sA + cA + aoff[fm] + ((colb + asub) ^ xorv));
#pragma unroll
                for (int p = 0; p < 4; p++)
                    LDSM4(bb[nxt][p], sB + cB + boff[p] + ((colb + bsub) ^ xorv));
            }
#pragma unroll
            for (int p = 0; p < 4; p++)
#pragma unroll
                for (int fm = 0; fm < 4; fm++) {
                    MMAF16(acc[fm][2 * p], ah[cur][fm], bb[cur][p][0], bb[cur][p][1]);
                    MMAF16(acc[fm][2 * p + 1], ah[cur][fm], bb[cur][p][2], bb[cur][p][3]);
                }
        }
        __syncthreads();
    }

    // -------- fused LSTM epilogue (gate-interleaved columns: fn&3 = gate) --------
    {
        int r_base = m0 + warp_m * 64 + (lane >> 2);
        int jb = (n0 >> 2) + warp_n * 16;
        float* outh = out;
        float* outc = out + (size_t)BDIM * HDIM;
#pragma unroll
        for (int fm = 0; fm < 4; fm++) {
#pragma unroll
            for (int q = 0; q < 2; q++) {
                int j0e = jb + q * 8 + (lane & 3) * 2;
                float2 vbi = *reinterpret_cast<const float2*>(bi + j0e);
                float2 vbf = *reinterpret_cast<const float2*>(bf + j0e);
                float2 vbo = *reinterpret_cast<const float2*>(bo + j0e);
                float2 vbc = *reinterpret_cast<const float2*>(bc + j0e);
                const float* gi = acc[fm][4 * q + 0];
                const float* gf = acc[fm][4 * q + 1];
                const float* go = acc[fm][4 * q + 2];
                const float* gg = acc[fm][4 * q + 3];
#pragma unroll
                for (int v2 = 0; v2 < 2; v2++) {
                    int row = r_base + fm * 16 + v2 * 8;
                    float2 cv = *reinterpret_cast<const float2*>(cin + (size_t)row * HDIM + j0e);
                    float2 hres, cres;
#pragma unroll
                    for (int e = 0; e < 2; e++) {
                        int idx = v2 * 2 + e;
                        float I = sigm(gi[idx] + (e ? vbi.y : vbi.x));
                        float F = sigm(gf[idx] + (e ? vbf.y : vbf.x));
                        float O = sigm(go[idx] + (e ? vbo.y : vbo.x));
                        float G = tanh_fast(gg[idx] + (e ? vbc.y : vbc.x));
                        float cc = (e ? cv.y : cv.x);
                        float ct = cc * F + I * G;
                        float ht = O * tanh_fast(ct);
                        if (e) { hres.y = ht; cres.y = ct; }
                        else   { hres.x = ht; cres.x = ct; }
                    }
                    *reinterpret_cast<float2*>(outh + (size_t)row * HDIM + j0e) = hres;
                    *reinterpret_cast<float2*>(outc + (size_t)row * HDIM + j0e) = cres;
                }
            }
        }
    }
}

// ---------------- host launch ----------------
extern "C" void kernel_launch(void* const* d_in, const int* in_sizes, int n_in,
                              void* d_out, int out_size) {
    const float* x = (const float*)d_in[0];
    const float* h = (const float*)d_in[1];
    const float* c = (const float*)d_in[2];
    const float* w_xi = (const float*)d_in[3];
    const float* w_xf = (const float*)d_in[4];
    const float* w_xo = (const float*)d_in[5];
    const float* w_xc = (const float*)d_in[6];
    const float* w_hi = (const float*)d_in[7];
    const float* w_hf = (const float*)d_in[8];
    const float* w_ho = (const float*)d_in[9];
    const float* w_hc = (const float*)d_in[10];
    const float* b_i = (const float*)d_in[11];
    const float* b_f = (const float*)d_in[12];
    const float* b_o = (const float*)d_in[13];
    const float* b_c = (const float*)d_in[14];
    float* out = (float*)d_out;

    cudaFuncSetAttribute(gemm_lstm_kernel, cudaFuncAttributeMaxDynamicSharedMemorySize, GEMM_SMEM);

    {
        size_t total = (size_t)BDIM * KDIM / 4;
        int blocks = (int)((total + 255) / 256);
        prep_a_kernel<<<blocks, 256>>>(x, h);
    }
    {
        dim3 grid(2048 / 64, 2048 / 32, 8);
        dim3 blk(32, 8);
        prep_w_kernel<<<grid, blk>>>(w_xi, w_xf, w_xo, w_xc, w_hi, w_hf, w_ho, w_hc);
    }
    gemm_lstm_kernel<<<1024, 256, GEMM_SMEM>>>(c, b_i, b_f, b_o, b_c, out);
    (void)in_sizes; (void)n_in; (void)out_size;
}

// round 7
// speedup vs baseline: 2.9737x; 1.0391x over previous
#include <cuda_runtime.h>
#include <cuda_fp16.h>
#include <stdint.h>
#include <stddef.h>

#define BDIM 4096
#define INDIM 2048
#define HDIM 2048
#define KDIM 4096   // IN + H
#define NDIM 8192   // 4 * H

// ---------------- scratch ----------------
__device__ __half g_A [(size_t)BDIM * KDIM];   // [x | h] as fp16
__device__ __half g_Bt[(size_t)NDIM * KDIM];   // permuted transposed weights as fp16

// ---------------- PTX helpers ----------------
__device__ __forceinline__ uint32_t smem_u32(const void* p) {
    uint32_t a;
    asm("{ .reg .u64 t; cvta.to.shared.u64 t, %1; cvt.u32.u64 %0, t; }" : "=r"(a) : "l"(p));
    return a;
}
#define SWZ128(o) ((o) ^ (((o) >> 3) & 0x70))

#define LDSM4(r, addr) \
    asm volatile("ldmatrix.sync.aligned.m8n8.x4.shared.b16 {%0,%1,%2,%3}, [%4];" \
        : "=r"((r)[0]), "=r"((r)[1]), "=r"((r)[2]), "=r"((r)[3]) : "r"(addr))

#define MMAF16(d, a, b0, b1) \
    asm volatile("mma.sync.aligned.m16n8k16.row.col.f32.f16.f16.f32 " \
        "{%0,%1,%2,%3}, {%4,%5,%6,%7}, {%8,%9}, {%0,%1,%2,%3};" \
        : "+f"((d)[0]), "+f"((d)[1]), "+f"((d)[2]), "+f"((d)[3]) \
        : "r"((a)[0]), "r"((a)[1]), "r"((a)[2]), "r"((a)[3]), "r"(b0), "r"(b1))

#define CP_ASYNC16(s, g) \
    asm volatile("cp.async.cg.shared.global [%0], [%1], 16;" :: "r"(s), "l"(g))
#define CP_COMMIT() asm volatile("cp.async.commit_group;" ::: "memory")
#define CP_WAITG(n) asm volatile("cp.async.wait_group %0;" :: "n"(n) : "memory")

// ---------------- Kernel 1: A = [x | h] -> fp16 ----------------
__global__ void prep_a_kernel(const float* __restrict__ x, const float* __restrict__ h) {
    size_t gid = (size_t)blockIdx.x * blockDim.x + threadIdx.x;
    size_t e = gid * 4;
    if (e >= (size_t)BDIM * KDIM) return;
    int b = (int)(e >> 12);
    int k = (int)(e & 4095);
    const float* src = (k < INDIM) ? (x + (size_t)b * INDIM + k)
                                   : (h + (size_t)b * HDIM + (k - INDIM));
    float4 v = *reinterpret_cast<const float4*>(src);
    __half2* p = reinterpret_cast<__half2*>(g_A + e);
    p[0] = __halves2half2(__float2half_rn(v.x), __float2half_rn(v.y));
    p[1] = __halves2half2(__float2half_rn(v.z), __float2half_rn(v.w));
}

// ---------------- Kernel 2: weights -> transposed, gate-permuted fp16 ----------------
// for gate g, output unit j:  n' = (j>>3)*32 + g*8 + (j&7)
__global__ void prep_w_kernel(
    const float* __restrict__ w0, const float* __restrict__ w1,
    const float* __restrict__ w2, const float* __restrict__ w3,
    const float* __restrict__ w4, const float* __restrict__ w5,
    const float* __restrict__ w6, const float* __restrict__ w7) {
    __shared__ float t[64][33];
    int z = blockIdx.z;
    const float* w;
    switch (z) {
        case 0: w = w0; break; case 1: w = w1; break;
        case 2: w = w2; break; case 3: w = w3; break;
        case 4: w = w4; break; case 5: w = w5; break;
        case 6: w = w6; break; default: w = w7; break;
    }
    int k0 = blockIdx.x * 64;
    int j0 = blockIdx.y * 32;
    int tx = threadIdx.x, ty = threadIdx.y;
#pragma unroll
    for (int i = 0; i < 8; i++) {
        int r = ty + i * 8;
        t[r][tx] = w[(size_t)(k0 + r) * 2048 + j0 + tx];
    }
    __syncthreads();
    int gate = z & 3;
    int koff = (z >> 2) * 2048;
#pragma unroll
    for (int i = 0; i < 4; i++) {
        int jj = ty + i * 8;
        int j = j0 + jj;
        __half v0 = __float2half_rn(t[2 * tx][jj]);
        __half v1 = __float2half_rn(t[2 * tx + 1][jj]);
        size_t np = (size_t)((j >> 3) * 32 + gate * 8 + (j & 7));
        size_t off = np * KDIM + koff + k0 + 2 * tx;
        *reinterpret_cast<__half2*>(g_Bt + off) = __halves2half2(v0, v1);
    }
}

// ---------------- Kernel 3: fp16 GEMM (512 threads, K-tile 128) + fused LSTM ----------------
#define TILE_M 128
#define TILE_N 256
#define TILE_K 128
#define NTHREADS 512
#define ST_A 0                     // 2 subtiles x 16KB = 32KB
#define ST_B (32 * 1024)           // 2 subtiles x 32KB = 64KB
#define STAGE_BYTES (96 * 1024)
#define GEMM_SMEM (2 * STAGE_BYTES)
#define K_ITERS (KDIM / TILE_K)    // 32

__device__ __forceinline__ void load_A_async(int m0, int it, uint32_t sdst, int tid) {
    int k0 = it * TILE_K;
#pragma unroll
    for (int i = 0; i < 4; i++) {
        int q = tid + i * NTHREADS;
        int r = q >> 4, cu = q & 15, c = cu >> 3, u = cu & 7;
        const void* gp = g_A + (size_t)(m0 + r) * KDIM + k0 + c * 64 + u * 8;
        uint32_t off = (uint32_t)(r * 128 + u * 16);
        CP_ASYNC16(sdst + (uint32_t)c * 16384 + SWZ128(off), gp);
    }
}
__device__ __forceinline__ void load_B_async(int n0, int it, uint32_t sdst, int tid) {
    int k0 = it * TILE_K;
#pragma unroll
    for (int i = 0; i < 8; i++) {
        int q = tid + i * NTHREADS;
        int r = q >> 4, cu = q & 15, c = cu >> 3, u = cu & 7;
        const void* gp = g_Bt + (size_t)(n0 + r) * KDIM + k0 + c * 64 + u * 8;
        uint32_t off = (uint32_t)(r * 128 + u * 16);
        CP_ASYNC16(sdst + (uint32_t)c * 32768 + SWZ128(off), gp);
    }
}

__device__ __forceinline__ float sigm(float v) { return 1.0f / (1.0f + __expf(-v)); }
__device__ __forceinline__ float tanh_fast(float v) { return 2.0f / (1.0f + __expf(-2.0f * v)) - 1.0f; }

__global__ __launch_bounds__(NTHREADS, 1) void gemm_lstm_kernel(
    const float* __restrict__ cin,
    const float* __restrict__ bi, const float* __restrict__ bf,
    const float* __restrict__ bo, const float* __restrict__ bc,
    float* __restrict__ out) {
    extern __shared__ char smem[];
    uint32_t sbase = smem_u32(smem);
    int tid = threadIdx.x;
    int wid = tid >> 5, lane = tid & 31;
    int mt = blockIdx.x & 31;       // M fast-varying: wave shares B tiles in L2
    int nt = blockIdx.x >> 5;
    int m0 = mt * TILE_M, n0 = nt * TILE_N;
    int warp_m = wid & 3, warp_n = wid >> 2;   // 4(M) x 4(N); warp tile 32x64

    uint32_t xorv = (uint32_t)((lane & 7) << 4);

    // A fragment addressing: 2 m16 frags
    uint32_t aoff[2];
#pragma unroll
    for (int fm = 0; fm < 2; fm++) {
        int arow = warp_m * 32 + fm * 16 + (lane & 15);
        aoff[fm] = (uint32_t)(arow * 128);
    }
    uint32_t asub = (uint32_t)((lane >> 4) << 4);

    // B fragment addressing: 4 x4-loads, each covers n-frags 2p,2p+1 over k16
    uint32_t boff[4];
#pragma unroll
    for (int p = 0; p < 4; p++) {
        int brow = warp_n * 64 + p * 16 + (lane & 7) + ((lane >> 4) & 1) * 8;
        boff[p] = (uint32_t)(brow * 128);
    }
    uint32_t bsub = (uint32_t)(((lane >> 3) & 1) << 4);

    float acc[2][8][4];
#pragma unroll
    for (int fm = 0; fm < 2; fm++)
#pragma unroll
        for (int fn = 0; fn < 8; fn++)
#pragma unroll
            for (int j = 0; j < 4; j++) acc[fm][fn][j] = 0.0f;

    // prologue: stage 0 (distance-1 prefetch, 2 stages)
    {
        load_A_async(m0, 0, sbase + ST_A, tid);
        load_B_async(n0, 0, sbase + ST_B, tid);
        CP_COMMIT();
    }

#pragma unroll 1
    for (int it = 0; it < K_ITERS; ++it) {
        if (it + 1 < K_ITERS) {
            uint32_t nb = sbase + (uint32_t)((it + 1) & 1) * STAGE_BYTES;
            load_A_async(m0, it + 1, nb + ST_A, tid);
            load_B_async(n0, it + 1, nb + ST_B, tid);
            CP_COMMIT();
            CP_WAITG(1);
        } else {
            CP_WAITG(0);
        }
        __syncthreads();

        uint32_t sb = sbase + (uint32_t)(it & 1) * STAGE_BYTES;
        uint32_t sA = sb + ST_A, sB = sb + ST_B;

#pragma unroll
        for (int ks = 0; ks < 8; ks++) {
            uint32_t cA = (uint32_t)(ks >> 2) * 16384;
            uint32_t cB = (uint32_t)(ks >> 2) * 32768;
            uint32_t colb = (uint32_t)((ks & 3) * 32);
            uint32_t ah[2][4], bb[4][4];
#pragma unroll
            for (int fm = 0; fm < 2; fm++)
                LDSM4(ah[fm], sA + cA + aoff[fm] + ((colb + asub) ^ xorv));
#pragma unroll
            for (int p = 0; p < 4; p++)
                LDSM4(bb[p], sB + cB + boff[p] + ((colb + bsub) ^ xorv));
#pragma unroll
            for (int p = 0; p < 4; p++)
#pragma unroll
                for (int fm = 0; fm < 2; fm++) {
                    MMAF16(acc[fm][2 * p], ah[fm], bb[p][0], bb[p][1]);
                    MMAF16(acc[fm][2 * p + 1], ah[fm], bb[p][2], bb[p][3]);
                }
        }
        __syncthreads();
    }

    // -------- fused LSTM epilogue (gate-interleaved columns: fn&3 = gate) --------
    {
        int r_base = m0 + warp_m * 32 + (lane >> 2);
        int jb = (n0 >> 2) + warp_n * 16;
        float* outh = out;
        float* outc = out + (size_t)BDIM * HDIM;
#pragma unroll
        for (int fm = 0; fm < 2; fm++) {
#pragma unroll
            for (int q = 0; q < 2; q++) {
                int j0e = jb + q * 8 + (lane & 3) * 2;
                float2 vbi = *reinterpret_cast<const float2*>(bi + j0e);
                float2 vbf = *reinterpret_cast<const float2*>(bf + j0e);
                float2 vbo = *reinterpret_cast<const float2*>(bo + j0e);
                float2 vbc = *reinterpret_cast<const float2*>(bc + j0e);
                const float* gi = acc[fm][4 * q + 0];
                const float* gf = acc[fm][4 * q + 1];
                const float* go = acc[fm][4 * q + 2];
                const float* gg = acc[fm][4 * q + 3];
#pragma unroll
                for (int v2 = 0; v2 < 2; v2++) {
                    int row = r_base + fm * 16 + v2 * 8;
                    float2 cv = *reinterpret_cast<const float2*>(cin + (size_t)row * HDIM + j0e);
                    float2 hres, cres;
#pragma unroll
                    for (int e = 0; e < 2; e++) {
                        int idx = v2 * 2 + e;
                        float I = sigm(gi[idx] + (e ? vbi.y : vbi.x));
                        float F = sigm(gf[idx] + (e ? vbf.y : vbf.x));
                        float O = sigm(go[idx] + (e ? vbo.y : vbo.x));
                        float G = tanh_fast(gg[idx] + (e ? vbc.y : vbc.x));
                        float cc = (e ? cv.y : cv.x);
                        float ct = cc * F + I * G;
                        float ht = O * tanh_fast(ct);
                        if (e) { hres.y = ht; cres.y = ct; }
                        else   { hres.x = ht; cres.x = ct; }
                    }
                    *reinterpret_cast<float2*>(outh + (size_t)row * HDIM + j0e) = hres;
                    *reinterpret_cast<float2*>(outc + (size_t)row * HDIM + j0e) = cres;
                }
            }
        }
    }
}

// ---------------- host launch ----------------
extern "C" void kernel_launch(void* const* d_in, const int* in_sizes, int n_in,
                              void* d_out, int out_size) {
    const float* x = (const float*)d_in[0];
    const float* h = (const float*)d_in[1];
    const float* c = (const float*)d_in[2];
    const float* w_xi = (const float*)d_in[3];
    const float* w_xf = (const float*)d_in[4];
    const float* w_xo = (const float*)d_in[5];
    const float* w_xc = (const float*)d_in[6];
    const float* w_hi = (const float*)d_in[7];
    const float* w_hf = (const float*)d_in[8];
    const float* w_ho = (const float*)d_in[9];
    const float* w_hc = (const float*)d_in[10];
    const float* b_i = (const float*)d_in[11];
    const float* b_f = (const float*)d_in[12];
    const float* b_o = (const float*)d_in[13];
    const float* b_c = (const float*)d_in[14];
    float* out = (float*)d_out;

    cudaFuncSetAttribute(gemm_lstm_kernel, cudaFuncAttributeMaxDynamicSharedMemorySize, GEMM_SMEM);

    {
        size_t total = (size_t)BDIM * KDIM / 4;
        int blocks = (int)((total + 255) / 256);
        prep_a_kernel<<<blocks, 256>>>(x, h);
    }
    {
        dim3 grid(2048 / 64, 2048 / 32, 8);
        dim3 blk(32, 8);
        prep_w_kernel<<<grid, blk>>>(w_xi, w_xf, w_xo, w_xc, w_hi, w_hf, w_ho, w_hc);
    }
    gemm_lstm_kernel<<<1024, NTHREADS, GEMM_SMEM>>>(c, b_i, b_f, b_o, b_c, out);
    (void)in_sizes; (void)n_in; (void)out_size;
}